// round 16
// baseline (speedup 1.0000x reference)
#include <cuda_runtime.h>
#include <cuda_bf16.h>
#include <cuda_fp16.h>
#include <math.h>
#include <stdint.h>

#define Nn 20000
#define Ee 100000
#define Epad 100096
#define Bb 128
#define FIN 14
#define DIM 64
#define EFEAT 4
#define MLPH 128
#define D2 4096   // DIM*DIM
#define G3 192    // 3*DIM

// GEMM tiling (R11 structure): B-resident col tile, stream TPB row tiles
#define TM 128
#define TN 128
#define RTILES 782           // Epad / TM
#define TPB 8                // row tiles per block
#define IDESC_EW 0x8200010u  // F32 acc, F16 a, F16 b, N=128, M=128

// SMEM layout (byte offsets from 1024-aligned base) — identical to R11
#define OFF_A     0          // 2 bufs x 32KB fp16 A (pre-swizzled)
#define OFF_B     65536      // 32KB fp16 B (pre-swizzled)
#define OFF_MBAR  98304      // 2 mbarriers
#define OFF_TPTR  98320
#define OFF_BIAS  98336      // 128 floats
#define SMEM_EW   99872      // incl. 1KB alignment slack; 2 CTAs/SM

// tcgen05 only exists on the arch-specific (103a) / family (103f) targets.
#if defined(__CUDA_ARCH__) && (__CUDA_ARCH__ >= 1000) && \
    (defined(__CUDA_ARCH_FEAT_SM103_ALL) || defined(__CUDA_ARCH_SPECIFIC__) || \
     defined(__CUDA_ARCH_FAMILY_SPECIFIC__))
#define HAS_TCGEN05 1
#else
#define HAS_TCGEN05 0
#endif

// ---------------- scratch (device globals; no allocation allowed) ----------
__device__ float g_out[Nn * DIM];
__device__ float g_h[Nn * DIM];
__device__ __half g_t16[Epad * MLPH];          // stored PRE-SWIZZLED per 128-row tile
__device__ __half g_w2t16[(size_t)D2 * MLPH];  // stored PRE-SWIZZLED per 128-row tile
__device__ __half g_ewh[(size_t)Ee * D2];      // 0.8 GB, fp16
__device__ float g_agg[Nn * DIM];
__device__ float g_cnt[Nn];
__device__ int   g_gs[Bb + 1];
__device__ float g_qstar[Bb * 2 * DIM];
__device__ float g_hl[Bb * DIM];
__device__ float g_cl[Bb * DIM];
__device__ float g_escr[Nn];

__device__ __forceinline__ float sigm(float x) { return 1.f / (1.f + expf(-x)); }

// byte address of fp16 element (row 0..127, k 0..127) inside 32KB blocked-SW128 tile
__device__ __forceinline__ size_t swz_off(int tile, int row, int k) {
    uint32_t boff = (uint32_t)(row * 128 + (k & 63) * 2);
    boff ^= (boff >> 3) & 0x70;
    return (size_t)tile * 32768 + (size_t)((k >> 6) * 16384) + boff;
}

#if HAS_TCGEN05
// ---------------- tcgen05 PTX helpers --------------------------------------
__device__ __forceinline__ uint32_t smem_u32(const void* p) {
    uint32_t a;
    asm("{ .reg .u64 t; cvta.to.shared.u64 t, %1; cvt.u32.u64 %0, t; }"
        : "=r"(a) : "l"(p));
    return a;
}
__device__ __forceinline__ uint32_t elect_one() {
    uint32_t pred;
    asm volatile("{\n\t.reg .pred p;\n\telect.sync _|p, 0xFFFFFFFF;\n\t"
                 "selp.b32 %0, 1, 0, p;\n\t}" : "=r"(pred));
    return pred;
}
__device__ __forceinline__ uint64_t make_desc(uint32_t addr) {
    // SW128, version=1 (Blackwell), SBO=64 (1024B per 8-row group), LBO=1
    return ((uint64_t)2 << 61) | ((uint64_t)1 << 46) | ((uint64_t)64 << 32) |
           ((uint64_t)1 << 16) | (((uint64_t)addr >> 4) & 0x3FFF);
}
__device__ __forceinline__ void mma_f16_ss(uint32_t d, uint64_t a, uint64_t b,
                                           uint32_t idesc, bool acc) {
    uint32_t en = acc ? 1u : 0u;
    asm volatile(
        "{\n\t.reg .pred p;\n\tsetp.ne.u32 p, %5, 0;\n\t"
        "tcgen05.mma.cta_group::1.kind::f16 [%0], %1, %2, %3, {%4, %4, %4, %4}, p;\n\t}"
        :: "r"(d), "l"(a), "l"(b), "r"(idesc), "r"(0u), "r"(en) : "memory");
}
#define TCG_ALLOC(smaddr, n) \
    asm volatile("tcgen05.alloc.cta_group::1.sync.aligned.shared::cta.b32 [%0], %1;" \
                 :: "r"(smaddr), "r"((uint32_t)(n)) : "memory")
#define TCG_RELINQUISH() \
    asm volatile("tcgen05.relinquish_alloc_permit.cta_group::1.sync.aligned;" ::: "memory")
#define TCG_DEALLOC(tmem, n) \
    asm volatile("tcgen05.dealloc.cta_group::1.sync.aligned.b32 %0, %1;" \
                 :: "r"(tmem), "r"((uint32_t)(n)))
#define TCG_COMMIT(mb) \
    asm volatile("tcgen05.commit.cta_group::1.mbarrier::arrive::one.shared::cluster.b64 [%0];" \
                 :: "r"(mb) : "memory")
#define TCG_FENCE_AFTER()  asm volatile("tcgen05.fence::after_thread_sync;" ::: "memory")
#define TCG_FENCE_BEFORE() asm volatile("tcgen05.fence::before_thread_sync;" ::: "memory")
#define TCG_WAIT_LD()      asm volatile("tcgen05.wait::ld.sync.aligned;" ::: "memory")
#define FENCE_ASYNC()      asm volatile("fence.proxy.async.shared::cta;" ::: "memory")
#define CP_ASYNC16(dst, src) \
    asm volatile("cp.async.cg.shared.global [%0], [%1], 16;" \
                 :: "r"(dst), "l"(src) : "memory")
#define CP_COMMIT() asm volatile("cp.async.commit_group;" ::: "memory")
#define CP_WAIT0()  asm volatile("cp.async.wait_group 0;" ::: "memory")
#define MBAR_INIT(mb, n) \
    asm volatile("mbarrier.init.shared.b64 [%0], %1;" :: "r"(mb), "r"((uint32_t)(n)) : "memory")
__device__ __forceinline__ void mbar_wait(uint32_t mb, uint32_t parity) {
    asm volatile(
        "{\n\t.reg .pred P1;\n\t"
        "W_%=:\n\t"
        "mbarrier.try_wait.parity.acquire.cta.shared::cta.b64 P1, [%0], %1, 0x989680;\n\t"
        "@P1 bra.uni D_%=;\n\t"
        "bra.uni W_%=;\n\t"
        "D_%=:\n\t}" :: "r"(mb), "r"(parity) : "memory");
}
#define LDTM32(r, addr) \
    asm volatile("tcgen05.ld.sync.aligned.32x32b.x32.b32 " \
        "{%0,%1,%2,%3,%4,%5,%6,%7,%8,%9,%10,%11,%12,%13,%14,%15," \
        "%16,%17,%18,%19,%20,%21,%22,%23,%24,%25,%26,%27,%28,%29,%30,%31}, [%32];" \
        : "=r"((r)[0]),"=r"((r)[1]),"=r"((r)[2]),"=r"((r)[3]), \
          "=r"((r)[4]),"=r"((r)[5]),"=r"((r)[6]),"=r"((r)[7]), \
          "=r"((r)[8]),"=r"((r)[9]),"=r"((r)[10]),"=r"((r)[11]), \
          "=r"((r)[12]),"=r"((r)[13]),"=r"((r)[14]),"=r"((r)[15]), \
          "=r"((r)[16]),"=r"((r)[17]),"=r"((r)[18]),"=r"((r)[19]), \
          "=r"((r)[20]),"=r"((r)[21]),"=r"((r)[22]),"=r"((r)[23]), \
          "=r"((r)[24]),"=r"((r)[25]),"=r"((r)[26]),"=r"((r)[27]), \
          "=r"((r)[28]),"=r"((r)[29]),"=r"((r)[30]),"=r"((r)[31]) \
        : "r"(addr))
#endif  // HAS_TCGEN05

// ---------------- lin0 + relu -> out, h; also zero g_agg -------------------
__global__ void k_lin0(const float* __restrict__ x, const float* __restrict__ w,
                       const float* __restrict__ b) {
    int idx = blockIdx.x * blockDim.x + threadIdx.x;
    if (idx >= Nn * DIM) return;
    int n = idx >> 6, d = idx & 63;
    float acc = b[d];
#pragma unroll
    for (int i = 0; i < FIN; i++) acc += x[n * FIN + i] * w[i * DIM + d];
    float v = fmaxf(acc, 0.f);
    g_out[idx] = v;
    g_h[idx] = v;
    g_agg[idx] = 0.f;    // msg1 accumulates into this (from the GEMM kernel)
}

// ---------------- edge MLP hidden -> fp16, stored pre-swizzled -------------
__global__ void k_edge_hidden(const float* __restrict__ ea, const float* __restrict__ w1,
                              const float* __restrict__ b1) {
    int idx = blockIdx.x * blockDim.x + threadIdx.x;
    if (idx >= Epad * MLPH) return;
    int e = idx >> 7, hc = idx & 127;
    float v = 0.f;
    if (e < Ee) {
        float acc = b1[hc];
#pragma unroll
        for (int f = 0; f < EFEAT; f++) acc += ea[e * EFEAT + f] * w1[f * MLPH + hc];
        v = fmaxf(acc, 0.f);
    }
    *(__half*)((char*)g_t16 + swz_off(e >> 7, e & 127, hc)) = __float2half(v);
}

// ---------------- W2 transpose -> fp16 [n][k], stored pre-swizzled ---------
__global__ void k_prep_w2t(const float* __restrict__ w2) {
    __shared__ float t[32][33];
    int nb = blockIdx.x * 32, kb = blockIdx.y * 32;
    int tx = threadIdx.x & 31, ty = threadIdx.x >> 5;  // 256 thr: ty 0..7
#pragma unroll
    for (int r = ty; r < 32; r += 8)
        t[r][tx] = w2[(size_t)(kb + r) * D2 + nb + tx];   // coalesced along n
    __syncthreads();
#pragma unroll
    for (int r = ty; r < 32; r += 8) {
        int n = nb + r, k = kb + tx;
        *(__half*)((char*)g_w2t16 + swz_off(n >> 7, n & 127, k)) = __float2half(t[tx][r]);
    }
}

// ---------------- ew GEMM (R11 pipeline) + register-fused msg step 1 -------
// B-resident col tile; A double-buffered via cp.async; direct-STG readout.
// During readout each thread also accumulates msg1 partials for its edge row
// in 32 registers per o-half and fires atomicAdds (REDG) into g_agg.
__global__ void __launch_bounds__(256, 2)
k_ew_mma(const float* __restrict__ bias, const int* __restrict__ ei) {
    extern __shared__ char smraw[];
    char* sb = (char*)(((uintptr_t)smraw + 1023) & ~(uintptr_t)1023);
    const int tid = threadIdx.x;
    const int col0 = blockIdx.x * TN;
    const int rt0 = blockIdx.y * TPB;
    const int NT = min(TPB, RTILES - rt0);
    const int i0 = col0 >> 6;        // feature pair covered by this col tile

#if HAS_TCGEN05
    uint32_t sb32 = smem_u32(sb);
    const int wid = tid >> 5, lane = tid & 31;
    float* s_bias = (float*)(sb + OFF_BIAS);

    if (wid == 4) {
        TCG_ALLOC(sb32 + OFF_TPTR, 256);
        TCG_RELINQUISH();
    }
    if (tid == 0) { MBAR_INIT(sb32 + OFF_MBAR, 1); MBAR_INIT(sb32 + OFF_MBAR + 8, 1); }
    if (tid < TN) s_bias[tid] = bias[col0 + tid];

    // ---- B resident: pre-swizzled tile -> plain contiguous copy ----
    {
        const char* src = (const char*)g_w2t16 + (size_t)blockIdx.x * 32768;
        for (int i = tid; i < 2048; i += 256)
            *(uint4*)(sb + OFF_B + i * 16) = *(const uint4*)(src + i * 16);
    }
    __syncthreads();

    uint32_t tmem;
    asm volatile("ld.shared.b32 %0, [%1];" : "=r"(tmem) : "r"(sb32 + OFF_TPTR));

    auto loadA_async = [&](int rt, int s) {
        const char* src = (const char*)g_t16 + (size_t)rt * 32768;
        for (int i = tid; i < 2048; i += 256)
            CP_ASYNC16(sb32 + OFF_A + s * 32768 + i * 16, src + i * 16);
        CP_COMMIT();
    };

    auto issueMMA = [&](int s, int db, uint32_t mb) {
        if (wid == 4 && elect_one()) {
            uint64_t aD = make_desc(sb32 + OFF_A + s * 32768);
            uint64_t bD = make_desc(sb32 + OFF_B);
#pragma unroll
            for (int ks = 0; ks < 8; ks++) {
                uint64_t off = (uint64_t)((ks >> 2) * 1024 + (ks & 3) * 2);
                mma_f16_ss(tmem + db * 128, aD + off, bD + off, IDESC_EW, ks > 0);
            }
            TCG_COMMIT(mb);
        }
    };

    const int m = (wid < 4) ? wid * 32 + lane : 0;

    // readout of row tile rt from TMEM db: ew store + fused msg1
    auto readout = [&](int db, int rt) {
        if (wid >= 4) return;
        int gr = rt * 128 + m;
        bool rok = gr < Ee;
        int srcn = rok ? __ldg(&ei[gr]) : 0;
        int dstn = rok ? __ldg(&ei[Ee + gr]) : 0;
        float x0 = 0.f, x1 = 0.f;
        if (rok) {
            float2 xv = *(const float2*)(g_out + (size_t)srcn * 64 + i0);
            x0 = xv.x; x1 = xv.y;
        }
        char* dst = (char*)g_ewh + (size_t)gr * 8192 + (size_t)col0 * 2;
        float* ag = g_agg + (size_t)dstn * 64;
        float mreg[32];
        // pairs: (cc=pair -> x0) then (cc=pair+2 -> x1), same o range per pair
#pragma unroll
        for (int pair = 0; pair < 2; pair++) {
#pragma unroll
            for (int half = 0; half < 2; half++) {
                int cc = pair + half * 2;
                float xi = half ? x1 : x0;
                uint32_t r[32];
                LDTM32(r, tmem + db * 128 + cc * 32);
                TCG_WAIT_LD();
                if (rok) {
#pragma unroll
                    for (int q = 0; q < 4; q++) {
                        const float* bq = s_bias + cc * 32 + q * 8;
                        float a0 = __uint_as_float(r[q*8+0]) + bq[0];
                        float a1 = __uint_as_float(r[q*8+1]) + bq[1];
                        float a2 = __uint_as_float(r[q*8+2]) + bq[2];
                        float a3 = __uint_as_float(r[q*8+3]) + bq[3];
                        float a4 = __uint_as_float(r[q*8+4]) + bq[4];
                        float a5 = __uint_as_float(r[q*8+5]) + bq[5];
                        float a6 = __uint_as_float(r[q*8+6]) + bq[6];
                        float a7 = __uint_as_float(r[q*8+7]) + bq[7];
                        float* mq = mreg + q * 8;
                        if (half == 0) {
                            mq[0] = xi * a0; mq[1] = xi * a1; mq[2] = xi * a2; mq[3] = xi * a3;
                            mq[4] = xi * a4; mq[5] = xi * a5; mq[6] = xi * a6; mq[7] = xi * a7;
                        } else {
                            mq[0] += xi * a0; mq[1] += xi * a1; mq[2] += xi * a2; mq[3] += xi * a3;
                            mq[4] += xi * a4; mq[5] += xi * a5; mq[6] += xi * a6; mq[7] += xi * a7;
                        }
                        uint4 v;
                        __half2 h0 = __floats2half2_rn(a0, a1);
                        __half2 h1 = __floats2half2_rn(a2, a3);
                        __half2 h2 = __floats2half2_rn(a4, a5);
                        __half2 h3 = __floats2half2_rn(a6, a7);
                        v.x = *(uint32_t*)&h0; v.y = *(uint32_t*)&h1;
                        v.z = *(uint32_t*)&h2; v.w = *(uint32_t*)&h3;
                        *(uint4*)(dst + cc * 64 + q * 16) = v;
                    }
                }
            }
            if (rok) {
                float* agp = ag + pair * 32;
#pragma unroll
                for (int o = 0; o < 32; o++) atomicAdd(agp + o, mreg[o]);
            }
        }
    };

    // ---- pipeline (identical skeleton to R11) ----
    loadA_async(rt0, 0);
    CP_WAIT0();
    __syncthreads();
    FENCE_ASYNC();
    issueMMA(0, 0, sb32 + OFF_MBAR);
    int ph0 = 0, ph1 = 0;
    for (int it = 1; it < NT; it++) {
        int s = it & 1, p = 1 - s;
        loadA_async(rt0 + it, s);      // async: in flight during wait+readout
        if (p == 0) { mbar_wait(sb32 + OFF_MBAR, ph0); ph0 ^= 1; }
        else        { mbar_wait(sb32 + OFF_MBAR + 8, ph1); ph1 ^= 1; }
        TCG_FENCE_AFTER();
        readout(p, rt0 + it - 1);      // overlaps cp.async
        CP_WAIT0();
        __syncthreads();
        FENCE_ASYNC();
        issueMMA(s, s, sb32 + OFF_MBAR + 8 * s);
    }
    int l = (NT - 1) & 1;
    if (l == 0) mbar_wait(sb32 + OFF_MBAR, ph0);
    else        mbar_wait(sb32 + OFF_MBAR + 8, ph1);
    TCG_FENCE_AFTER();
    readout(l, rt0 + NT - 1);
    __syncthreads();
    if (wid == 4) TCG_DEALLOC(tmem, 256);

#else  // ---------------- plain sm_103 fallback (never selected) ----------
    for (int rt = rt0; rt < rt0 + NT; rt++) {
        for (int idx = tid; idx < 128 * 128; idx += 256) {
            int r = idx >> 7, c = idx & 127;
            int gr = rt * 128 + r;
            if (gr >= Ee) continue;
            int cn = col0 + c;
            float acc = bias[cn];
            for (int k = 0; k < 128; k++) {
                float av = __half2float(*(const __half*)((const char*)g_t16 +
                               swz_off(gr >> 7, gr & 127, k)));
                float bv = __half2float(*(const __half*)((const char*)g_w2t16 +
                               swz_off(cn >> 7, cn & 127, k)));
                acc += av * bv;
            }
            g_ewh[(size_t)gr * D2 + cn] = __float2half(acc);
            int i = cn >> 6, o = cn & 63;
            int sn = ei[gr], dn = ei[Ee + gr];
            atomicAdd(&g_agg[(size_t)dn * 64 + o], g_out[(size_t)sn * 64 + i] * acc);
        }
    }
#endif
}

// ---------------- zero helpers --------------------------------------------
__global__ void k_zero_cnt() {
    int idx = blockIdx.x * blockDim.x + threadIdx.x;
    if (idx < Nn) g_cnt[idx] = 0.f;
}
__global__ void k_zero_s2s() {
    int idx = blockIdx.x * blockDim.x + threadIdx.x;
    if (idx < Bb * 2 * DIM) g_qstar[idx] = 0.f;
    if (idx < Bb * DIM) { g_hl[idx] = 0.f; g_cl[idx] = 0.f; }
}

// ---------------- in-degree counts -----------------------------------------
__global__ void k_count(const int* __restrict__ ei) {
    int e = blockIdx.x * blockDim.x + threadIdx.x;
    if (e < Ee) atomicAdd(&g_cnt[ei[Ee + e]], 1.f);
}

// ---------------- per-edge matmul + scatter-add (fp16 ew, warp per edge) ---
__global__ void k_msg(const int* __restrict__ ei) {
    int eg = threadIdx.x >> 5;      // 8 edges per block, warp per edge
    int j = threadIdx.x & 31;       // column-pair index
    int e = blockIdx.x * 8 + eg;
    __shared__ float xs[8][64];
    if (e >= Ee) return;
    int src = ei[e];
    int dst = ei[Ee + e];
    xs[eg][j] = g_out[src * DIM + j];
    xs[eg][j + 32] = g_out[src * DIM + j + 32];
    __syncwarp();
    const __half2* ew = (const __half2*)(g_ewh + (size_t)e * D2) + j;
    float acc0 = 0.f, acc1 = 0.f;
#pragma unroll 16
    for (int i = 0; i < 64; i++) {
        float2 w = __half22float2(ew[i * 32]);
        float xv = xs[eg][i];
        acc0 += xv * w.x;
        acc1 += xv * w.y;
    }
    atomicAdd(&g_agg[dst * DIM + 2 * j], acc0);
    atomicAdd(&g_agg[dst * DIM + 2 * j + 1], acc1);
}

// ---------------- fused node update: conv + GRU gates + GRU + agg-zero -----
__global__ void __launch_bounds__(192)
k_node_update(const float* __restrict__ cr, const float* __restrict__ cb,
              const float* __restrict__ wi, const float* __restrict__ wh,
              const float* __restrict__ bi, const float* __restrict__ bh) {
    int t = threadIdx.x;            // 192 threads
    int n0 = blockIdx.x * 16;
    __shared__ float os[16][DIM], hs[16][DIM], ms[16][DIM];
    __shared__ float gis[16][G3], ghs[16][G3];

    for (int idx = t; idx < 16 * DIM; idx += 192) {
        int r = idx >> 6, d = idx & 63;
        int n = n0 + r;
        float ov = 0.f, hv = 0.f;
        if (n < Nn) { ov = g_out[n * DIM + d]; hv = g_h[n * DIM + d]; }
        os[r][d] = ov;
        hs[r][d] = hv;
    }
    __syncthreads();

    {
        int d = t & 63, p = t >> 6;
        float bd = cb[d];
        for (int r = p; r < 16; r += 3) {
            int n = n0 + r;
            float acc = 0.f;
#pragma unroll 8
            for (int i = 0; i < 64; i++) acc += os[r][i] * cr[i * DIM + d];
            float mval = 0.f;
            if (n < Nn) {
                float c = fmaxf(g_cnt[n], 1.f);
                mval = fmaxf(g_agg[n * DIM + d] / c + acc + bd, 0.f);
                g_agg[n * DIM + d] = 0.f;   // ready for next msg step
            }
            ms[r][d] = mval;
        }
    }
    __syncthreads();

    {
        int g = t;
        float ai[16], ah[16];
#pragma unroll
        for (int r = 0; r < 16; r++) { ai[r] = 0.f; ah[r] = 0.f; }
        for (int i = 0; i < 64; i++) {
            float wiv = wi[i * G3 + g], whv = wh[i * G3 + g];
#pragma unroll
            for (int r = 0; r < 16; r++) {
                ai[r] += ms[r][i] * wiv;
                ah[r] += hs[r][i] * whv;
            }
        }
        float biv = bi[g], bhv = bh[g];
#pragma unroll
        for (int r = 0; r < 16; r++) {
            gis[r][g] = ai[r] + biv;
            ghs[r][g] = ah[r] + bhv;
        }
    }
    __syncthreads();

    {
        int d = t & 63, p = t >> 6;
        for (int r = p; r < 16; r += 3) {
            int n = n0 + r;
            if (n >= Nn) continue;
            float rg = sigm(gis[r][d] + ghs[r][d]);
            float z = sigm(gis[r][64 + d] + ghs[r][64 + d]);
            float nn = tanhf(gis[r][128 + d] + rg * ghs[r][128 + d]);
            float h = hs[r][d];
            float hn = (1.f - z) * nn + z * h;
            g_h[n * DIM + d] = hn;
            g_out[n * DIM + d] = hn;
        }
    }
}

// ---------------- per-graph node ranges (batch is sorted) ------------------
__global__ void k_ranges(const int* __restrict__ batch) {
    int n = blockIdx.x * blockDim.x + threadIdx.x;
    if (n >= Nn) return;
    int bn = batch[n];
    int bp = (n == 0) ? -1 : batch[n - 1];
    for (int b = bp + 1; b <= bn; b++) g_gs[b] = n;
    if (n == Nn - 1)
        for (int b = bn + 1; b <= Bb; b++) g_gs[b] = Nn;
}

// ---------------- Set2Set LSTM cell ----------------------------------------
__global__ void k_lstm(const float* __restrict__ wi, const float* __restrict__ wh,
                       const float* __restrict__ bi, const float* __restrict__ bh) {
    int b = blockIdx.x;
    int g = threadIdx.x;            // 256 threads
    __shared__ float qs[128], hls[64], gate[256];
    if (g < 128) qs[g] = g_qstar[b * 128 + g];
    if (g < 64) hls[g] = g_hl[b * 64 + g];
    __syncthreads();
    float acc = bi[g] + bh[g];
    for (int i = 0; i < 128; i++) acc += qs[i] * wi[i * 256 + g];
    for (int i = 0; i < 64; i++) acc += hls[i] * wh[i * 256 + g];
    gate[g] = acc;
    __syncthreads();
    if (g < 64) {
        float iv = sigm(gate[g]);
        float fv = sigm(gate[64 + g]);
        float gv = tanhf(gate[128 + g]);
        float ov = sigm(gate[192 + g]);
        float c = fv * g_cl[b * 64 + g] + iv * gv;
        g_cl[b * 64 + g] = c;
        g_hl[b * 64 + g] = ov * tanhf(c);
    }
}

// ---------------- Set2Set attention + readout ------------------------------
__global__ void k_attend() {
    int b = blockIdx.x;
    int t = threadIdx.x;            // 256 threads
    __shared__ float q[64];
    __shared__ float red[256];
    __shared__ float rs[4][64];
    if (t < 64) q[t] = g_hl[b * 64 + t];
    int s = g_gs[b], epos = g_gs[b + 1];
    __syncthreads();

    float lmax = -INFINITY;
    for (int n = s + t; n < epos; n += 256) {
        const float* orow = g_out + (size_t)n * 64;
        float acc = 0.f;
#pragma unroll
        for (int d = 0; d < 64; d++) acc += orow[d] * q[d];
        g_escr[n] = acc;
        lmax = fmaxf(lmax, acc);
    }
    red[t] = lmax;
    __syncthreads();
    for (int st = 128; st > 0; st >>= 1) {
        if (t < st) red[t] = fmaxf(red[t], red[t + st]);
        __syncthreads();
    }
    float emax = red[0];
    __syncthreads();

    float lsum = 0.f;
    for (int n = s + t; n < epos; n += 256) {
        float a = expf(g_escr[n] - emax);
        g_escr[n] = a;
        lsum += a;
    }
    red[t] = lsum;
    __syncthreads();
    for (int st = 128; st > 0; st >>= 1) {
        if (t < st) red[t] += red[t + st];
        __syncthreads();
    }
    float inv = 1.f / fmaxf(red[0], 1e-16f);
    __syncthreads();

    int d = t & 63, slot = t >> 6;
    float acc = 0.f;
    for (int n = s + slot; n < epos; n += 4) acc += g_escr[n] * g_out[(size_t)n * 64 + d];
    rs[slot][d] = acc;
    __syncthreads();
    if (t < 64) {
        float r = (rs[0][t] + rs[1][t] + rs[2][t] + rs[3][t]) * inv;
        g_qstar[b * 128 + t] = q[t];
        g_qstar[b * 128 + 64 + t] = r;
    }
}

// ---------------- output head ----------------------------------------------
__global__ void k_head(const float* __restrict__ w1, const float* __restrict__ b1,
                       const float* __restrict__ w2, const float* __restrict__ b2,
                       float* __restrict__ out) {
    int b = blockIdx.x;
    int d = threadIdx.x;            // 64 threads
    __shared__ float qs[128];
    __shared__ float red[64];
    qs[d] = g_qstar[b * 128 + d];
    qs[64 + d] = g_qstar[b * 128 + 64 + d];
    __syncthreads();
    float acc = b1[d];
    for (int i = 0; i < 128; i++) acc += qs[i] * w1[i * 64 + d];
    float h1 = fmaxf(acc, 0.f);
    red[d] = h1 * w2[d];
    __syncthreads();
    for (int st = 32; st > 0; st >>= 1) {
        if (d < st) red[d] += red[d + st];
        __syncthreads();
    }
    if (d == 0) out[b] = red[0] + b2[0];
}

// ---------------- launch ----------------------------------------------------
extern "C" void kernel_launch(void* const* d_in, const int* in_sizes, int n_in,
                              void* d_out, int out_size) {
    const float* x        = (const float*)d_in[0];
    const float* ea       = (const float*)d_in[1];
    const int*   ei       = (const int*)d_in[2];
    const int*   batch    = (const int*)d_in[3];
    const float* lin0_w   = (const float*)d_in[4];
    const float* lin0_b   = (const float*)d_in[5];
    const float* mlp_w1   = (const float*)d_in[6];
    const float* mlp_b1   = (const float*)d_in[7];
    const float* mlp_w2   = (const float*)d_in[8];
    const float* mlp_b2   = (const float*)d_in[9];
    const float* conv_root= (const float*)d_in[10];
    const float* conv_bias= (const float*)d_in[11];
    const float* gru_wi   = (const float*)d_in[12];
    const float* gru_wh   = (const float*)d_in[13];
    const float* gru_bi   = (const float*)d_in[14];
    const float* gru_bh   = (const float*)d_in[15];
    const float* lstm_wi  = (const float*)d_in[16];
    const float* lstm_wh  = (const float*)d_in[17];
    const float* lstm_bi  = (const float*)d_in[18];
    const float* lstm_bh  = (const float*)d_in[19];
    const float* lin1_w   = (const float*)d_in[20];
    const float* lin1_b   = (const float*)d_in[21];
    const float* lin2_w   = (const float*)d_in[22];
    const float* lin2_b   = (const float*)d_in[23];
    float* out = (float*)d_out;

    cudaFuncSetAttribute(k_ew_mma, cudaFuncAttributeMaxDynamicSharedMemorySize, SMEM_EW);

    // k_ew_mma stays at launch idx 3 (the profiled slot)
    k_lin0<<<(Nn * DIM + 255) / 256, 256>>>(x, lin0_w, lin0_b);
    k_edge_hidden<<<(Epad * MLPH + 255) / 256, 256>>>(ea, mlp_w1, mlp_b1);
    {
        dim3 tg(D2 / 32, MLPH / 32);
        k_prep_w2t<<<tg, 256>>>(mlp_w2);
    }
    {
        dim3 grid(D2 / TN, (RTILES + TPB - 1) / TPB);
        k_ew_mma<<<grid, 256, SMEM_EW>>>(mlp_b2, ei);   // GEMM + fused msg step 1
    }
    k_zero_cnt<<<(Nn + 255) / 256, 256>>>();
    k_count<<<(Ee + 255) / 256, 256>>>(ei);

    // finish step 1, then steps 2..3
    k_node_update<<<(Nn + 15) / 16, 192>>>(conv_root, conv_bias, gru_wi, gru_wh,
                                           gru_bi, gru_bh);
    for (int s = 1; s < 3; s++) {
        k_msg<<<(Ee + 7) / 8, 256>>>(ei);
        k_node_update<<<(Nn + 15) / 16, 192>>>(conv_root, conv_bias, gru_wi, gru_wh,
                                               gru_bi, gru_bh);
    }

    k_ranges<<<(Nn + 255) / 256, 256>>>(batch);
    k_zero_s2s<<<(Bb * 2 * DIM + 255) / 256, 256>>>();
    for (int it = 0; it < 3; it++) {
        k_lstm<<<Bb, 256>>>(lstm_wi, lstm_wh, lstm_bi, lstm_bh);
        k_attend<<<Bb, 256>>>();
    }
    k_head<<<Bb, 64>>>(lin1_w, lin1_b, lin2_w, lin2_b, out);
}

// round 17
// speedup vs baseline: 1.8546x; 1.8546x over previous
#include <cuda_runtime.h>
#include <cuda_bf16.h>
#include <cuda_fp16.h>
#include <math.h>
#include <stdint.h>

#define Nn 20000
#define Ee 100000
#define Epad 100096
#define Bb 128
#define FIN 14
#define DIM 64
#define EFEAT 4
#define MLPH 128
#define D2 4096   // DIM*DIM
#define G3 192    // 3*DIM

// GEMM tiling: B-resident col tile, stream TPB row tiles (R11 champion)
#define TM 128
#define TN 128
#define RTILES 782           // Epad / TM
#define TPB 8                // row tiles per block
#define IDESC_EW 0x8200010u  // F32 acc, F16 a, F16 b, N=128, M=128

// SMEM layout (byte offsets from 1024-aligned base)
#define OFF_A     0          // 2 bufs x 32KB fp16 A (pre-swizzled)
#define OFF_B     65536      // 32KB fp16 B (pre-swizzled)
#define OFF_MBAR  98304      // 2 mbarriers
#define OFF_TPTR  98320
#define OFF_BIAS  98336      // 128 floats
#define SMEM_EW   99872      // incl. 1KB alignment slack; 2 CTAs/SM

// tcgen05 only exists on the arch-specific (103a) / family (103f) targets.
#if defined(__CUDA_ARCH__) && (__CUDA_ARCH__ >= 1000) && \
    (defined(__CUDA_ARCH_FEAT_SM103_ALL) || defined(__CUDA_ARCH_SPECIFIC__) || \
     defined(__CUDA_ARCH_FAMILY_SPECIFIC__))
#define HAS_TCGEN05 1
#else
#define HAS_TCGEN05 0
#endif

// ---------------- scratch (device globals; no allocation allowed) ----------
__device__ float g_out[Nn * DIM];
__device__ float g_h[Nn * DIM];
__device__ __half g_t16[Epad * MLPH];          // stored PRE-SWIZZLED per 128-row tile
__device__ __half g_w2t16[(size_t)D2 * MLPH];  // stored PRE-SWIZZLED per 128-row tile
__device__ __half g_ewh[(size_t)Ee * D2];      // 0.8 GB, fp16
__device__ float g_agg[Nn * DIM];
__device__ float g_cnt[Nn];
__device__ int   g_gs[Bb + 1];
__device__ float g_qstar[Bb * 2 * DIM];
__device__ float g_hl[Bb * DIM];
__device__ float g_cl[Bb * DIM];
__device__ float g_escr[Nn];

__device__ __forceinline__ float sigm(float x) { return 1.f / (1.f + expf(-x)); }

// byte address of fp16 element (row 0..127, k 0..127) inside 32KB blocked-SW128 tile
__device__ __forceinline__ size_t swz_off(int tile, int row, int k) {
    uint32_t boff = (uint32_t)(row * 128 + (k & 63) * 2);
    boff ^= (boff >> 3) & 0x70;
    return (size_t)tile * 32768 + (size_t)((k >> 6) * 16384) + boff;
}

#if HAS_TCGEN05
// ---------------- tcgen05 PTX helpers --------------------------------------
__device__ __forceinline__ uint32_t smem_u32(const void* p) {
    uint32_t a;
    asm("{ .reg .u64 t; cvta.to.shared.u64 t, %1; cvt.u32.u64 %0, t; }"
        : "=r"(a) : "l"(p));
    return a;
}
__device__ __forceinline__ uint32_t elect_one() {
    uint32_t pred;
    asm volatile("{\n\t.reg .pred p;\n\telect.sync _|p, 0xFFFFFFFF;\n\t"
                 "selp.b32 %0, 1, 0, p;\n\t}" : "=r"(pred));
    return pred;
}
__device__ __forceinline__ uint64_t make_desc(uint32_t addr) {
    // SW128, version=1 (Blackwell), SBO=64 (1024B per 8-row group), LBO=1
    return ((uint64_t)2 << 61) | ((uint64_t)1 << 46) | ((uint64_t)64 << 32) |
           ((uint64_t)1 << 16) | (((uint64_t)addr >> 4) & 0x3FFF);
}
__device__ __forceinline__ void mma_f16_ss(uint32_t d, uint64_t a, uint64_t b,
                                           uint32_t idesc, bool acc) {
    uint32_t en = acc ? 1u : 0u;
    asm volatile(
        "{\n\t.reg .pred p;\n\tsetp.ne.u32 p, %5, 0;\n\t"
        "tcgen05.mma.cta_group::1.kind::f16 [%0], %1, %2, %3, {%4, %4, %4, %4}, p;\n\t}"
        :: "r"(d), "l"(a), "l"(b), "r"(idesc), "r"(0u), "r"(en) : "memory");
}
#define TCG_ALLOC(smaddr, n) \
    asm volatile("tcgen05.alloc.cta_group::1.sync.aligned.shared::cta.b32 [%0], %1;" \
                 :: "r"(smaddr), "r"((uint32_t)(n)) : "memory")
#define TCG_RELINQUISH() \
    asm volatile("tcgen05.relinquish_alloc_permit.cta_group::1.sync.aligned;" ::: "memory")
#define TCG_DEALLOC(tmem, n) \
    asm volatile("tcgen05.dealloc.cta_group::1.sync.aligned.b32 %0, %1;" \
                 :: "r"(tmem), "r"((uint32_t)(n)))
#define TCG_COMMIT(mb) \
    asm volatile("tcgen05.commit.cta_group::1.mbarrier::arrive::one.shared::cluster.b64 [%0];" \
                 :: "r"(mb) : "memory")
#define TCG_FENCE_AFTER()  asm volatile("tcgen05.fence::after_thread_sync;" ::: "memory")
#define TCG_FENCE_BEFORE() asm volatile("tcgen05.fence::before_thread_sync;" ::: "memory")
#define TCG_WAIT_LD()      asm volatile("tcgen05.wait::ld.sync.aligned;" ::: "memory")
#define FENCE_ASYNC()      asm volatile("fence.proxy.async.shared::cta;" ::: "memory")
#define CP_ASYNC16(dst, src) \
    asm volatile("cp.async.cg.shared.global [%0], [%1], 16;" \
                 :: "r"(dst), "l"(src) : "memory")
#define CP_COMMIT() asm volatile("cp.async.commit_group;" ::: "memory")
#define CP_WAIT0()  asm volatile("cp.async.wait_group 0;" ::: "memory")
#define MBAR_INIT(mb, n) \
    asm volatile("mbarrier.init.shared.b64 [%0], %1;" :: "r"(mb), "r"((uint32_t)(n)) : "memory")
__device__ __forceinline__ void mbar_wait(uint32_t mb, uint32_t parity) {
    asm volatile(
        "{\n\t.reg .pred P1;\n\t"
        "W_%=:\n\t"
        "mbarrier.try_wait.parity.acquire.cta.shared::cta.b64 P1, [%0], %1, 0x989680;\n\t"
        "@P1 bra.uni D_%=;\n\t"
        "bra.uni W_%=;\n\t"
        "D_%=:\n\t}" :: "r"(mb), "r"(parity) : "memory");
}
#define LDTM32(r, addr) \
    asm volatile("tcgen05.ld.sync.aligned.32x32b.x32.b32 " \
        "{%0,%1,%2,%3,%4,%5,%6,%7,%8,%9,%10,%11,%12,%13,%14,%15," \
        "%16,%17,%18,%19,%20,%21,%22,%23,%24,%25,%26,%27,%28,%29,%30,%31}, [%32];" \
        : "=r"((r)[0]),"=r"((r)[1]),"=r"((r)[2]),"=r"((r)[3]), \
          "=r"((r)[4]),"=r"((r)[5]),"=r"((r)[6]),"=r"((r)[7]), \
          "=r"((r)[8]),"=r"((r)[9]),"=r"((r)[10]),"=r"((r)[11]), \
          "=r"((r)[12]),"=r"((r)[13]),"=r"((r)[14]),"=r"((r)[15]), \
          "=r"((r)[16]),"=r"((r)[17]),"=r"((r)[18]),"=r"((r)[19]), \
          "=r"((r)[20]),"=r"((r)[21]),"=r"((r)[22]),"=r"((r)[23]), \
          "=r"((r)[24]),"=r"((r)[25]),"=r"((r)[26]),"=r"((r)[27]), \
          "=r"((r)[28]),"=r"((r)[29]),"=r"((r)[30]),"=r"((r)[31]) \
        : "r"(addr))
#endif  // HAS_TCGEN05

// ---------------- lin0 + relu -> out, h; zero g_agg ------------------------
__global__ void k_lin0(const float* __restrict__ x, const float* __restrict__ w,
                       const float* __restrict__ b) {
    int idx = blockIdx.x * blockDim.x + threadIdx.x;
    if (idx >= Nn * DIM) return;
    int n = idx >> 6, d = idx & 63;
    float acc = b[d];
#pragma unroll
    for (int i = 0; i < FIN; i++) acc += x[n * FIN + i] * w[i * DIM + d];
    float v = fmaxf(acc, 0.f);
    g_out[idx] = v;
    g_h[idx] = v;
    g_agg[idx] = 0.f;
}

// ---------------- edge MLP hidden -> fp16, stored pre-swizzled -------------
__global__ void k_edge_hidden(const float* __restrict__ ea, const float* __restrict__ w1,
                              const float* __restrict__ b1) {
    int idx = blockIdx.x * blockDim.x + threadIdx.x;
    if (idx >= Epad * MLPH) return;
    int e = idx >> 7, hc = idx & 127;
    float v = 0.f;
    if (e < Ee) {
        float acc = b1[hc];
#pragma unroll
        for (int f = 0; f < EFEAT; f++) acc += ea[e * EFEAT + f] * w1[f * MLPH + hc];
        v = fmaxf(acc, 0.f);
    }
    *(__half*)((char*)g_t16 + swz_off(e >> 7, e & 127, hc)) = __float2half(v);
}

// ---------------- W2 transpose -> fp16 [n][k], stored pre-swizzled ---------
__global__ void k_prep_w2t(const float* __restrict__ w2) {
    __shared__ float t[32][33];
    int nb = blockIdx.x * 32, kb = blockIdx.y * 32;
    int tx = threadIdx.x & 31, ty = threadIdx.x >> 5;  // 256 thr: ty 0..7
#pragma unroll
    for (int r = ty; r < 32; r += 8)
        t[r][tx] = w2[(size_t)(kb + r) * D2 + nb + tx];   // coalesced along n
    __syncthreads();
#pragma unroll
    for (int r = ty; r < 32; r += 8) {
        int n = nb + r, k = kb + tx;
        *(__half*)((char*)g_w2t16 + swz_off(n >> 7, n & 127, k)) = __float2half(t[tx][r]);
    }
}

// ---------------- ew GEMM: pipelined tcgen05 fp16, cp.async, direct STG ----
__global__ void __launch_bounds__(256, 2)
k_ew_mma(const float* __restrict__ bias) {
    extern __shared__ char smraw[];
    char* sb = (char*)(((uintptr_t)smraw + 1023) & ~(uintptr_t)1023);
    const int tid = threadIdx.x;
    const int col0 = blockIdx.x * TN;
    const int rt0 = blockIdx.y * TPB;
    const int NT = min(TPB, RTILES - rt0);

#if HAS_TCGEN05
    uint32_t sb32 = smem_u32(sb);
    const int wid = tid >> 5, lane = tid & 31;
    float* s_bias = (float*)(sb + OFF_BIAS);

    if (wid == 4) {
        TCG_ALLOC(sb32 + OFF_TPTR, 256);
        TCG_RELINQUISH();   // release alloc permit so the co-resident CTA can alloc
    }
    if (tid == 0) { MBAR_INIT(sb32 + OFF_MBAR, 1); MBAR_INIT(sb32 + OFF_MBAR + 8, 1); }
    if (tid < TN) s_bias[tid] = bias[col0 + tid];

    // ---- B resident: pre-swizzled tile -> plain contiguous copy ----
    {
        const char* src = (const char*)g_w2t16 + (size_t)blockIdx.x * 32768;
        for (int i = tid; i < 2048; i += 256)
            *(uint4*)(sb + OFF_B + i * 16) = *(const uint4*)(src + i * 16);
    }
    __syncthreads();

    uint32_t tmem;
    asm volatile("ld.shared.b32 %0, [%1];" : "=r"(tmem) : "r"(sb32 + OFF_TPTR));

    auto loadA_async = [&](int rt, int s) {
        const char* src = (const char*)g_t16 + (size_t)rt * 32768;
        for (int i = tid; i < 2048; i += 256)
            CP_ASYNC16(sb32 + OFF_A + s * 32768 + i * 16, src + i * 16);
        CP_COMMIT();
    };

    auto issueMMA = [&](int s, int db, uint32_t mb) {
        if (wid == 4 && elect_one()) {
            uint64_t aD = make_desc(sb32 + OFF_A + s * 32768);
            uint64_t bD = make_desc(sb32 + OFF_B);
#pragma unroll
            for (int ks = 0; ks < 8; ks++) {
                uint64_t off = (uint64_t)((ks >> 2) * 1024 + (ks & 3) * 2);
                mma_f16_ss(tmem + db * 128, aD + off, bD + off, IDESC_EW, ks > 0);
            }
            TCG_COMMIT(mb);
        }
    };

    // direct-STG readout: warps 0-3, each thread owns row m, writes 64B/chunk
    auto readout = [&](int db, int rt) {
        if (wid < 4) {
            int m = wid * 32 + lane;
            int gr = rt * 128 + m;
            char* dst = (char*)g_ewh + (size_t)gr * 8192 + (size_t)col0 * 2;
#pragma unroll
            for (int cc = 0; cc < 4; cc++) {
                uint32_t r[32];
                LDTM32(r, tmem + db * 128 + cc * 32);
                TCG_WAIT_LD();
                if (gr < Ee) {
#pragma unroll
                    for (int q = 0; q < 4; q++) {
                        uint4 v;
                        float a0 = __uint_as_float(r[q*8+0]) + s_bias[cc*32+q*8+0];
                        float a1 = __uint_as_float(r[q*8+1]) + s_bias[cc*32+q*8+1];
                        float a2 = __uint_as_float(r[q*8+2]) + s_bias[cc*32+q*8+2];
                        float a3 = __uint_as_float(r[q*8+3]) + s_bias[cc*32+q*8+3];
                        float a4 = __uint_as_float(r[q*8+4]) + s_bias[cc*32+q*8+4];
                        float a5 = __uint_as_float(r[q*8+5]) + s_bias[cc*32+q*8+5];
                        float a6 = __uint_as_float(r[q*8+6]) + s_bias[cc*32+q*8+6];
                        float a7 = __uint_as_float(r[q*8+7]) + s_bias[cc*32+q*8+7];
                        __half2 h0 = __floats2half2_rn(a0, a1);
                        __half2 h1 = __floats2half2_rn(a2, a3);
                        __half2 h2 = __floats2half2_rn(a4, a5);
                        __half2 h3 = __floats2half2_rn(a6, a7);
                        v.x = *(uint32_t*)&h0; v.y = *(uint32_t*)&h1;
                        v.z = *(uint32_t*)&h2; v.w = *(uint32_t*)&h3;
                        *(uint4*)(dst + cc * 64 + q * 16) = v;
                    }
                }
            }
        }
    };

    // ---- pipeline: cp.async(it) overlaps readout(it-1) ----
    loadA_async(rt0, 0);
    CP_WAIT0();
    __syncthreads();
    FENCE_ASYNC();
    issueMMA(0, 0, sb32 + OFF_MBAR);
    int ph0 = 0, ph1 = 0;
    for (int it = 1; it < NT; it++) {
        int s = it & 1, p = 1 - s;
        loadA_async(rt0 + it, s);      // async: in flight during wait+readout
        if (p == 0) { mbar_wait(sb32 + OFF_MBAR, ph0); ph0 ^= 1; }
        else        { mbar_wait(sb32 + OFF_MBAR + 8, ph1); ph1 ^= 1; }
        TCG_FENCE_AFTER();
        readout(p, rt0 + it - 1);      // overlaps cp.async
        CP_WAIT0();
        __syncthreads();               // A buf s ready + readout(p) done everywhere
        FENCE_ASYNC();
        issueMMA(s, s, sb32 + OFF_MBAR + 8 * s);
    }
    int l = (NT - 1) & 1;
    if (l == 0) mbar_wait(sb32 + OFF_MBAR, ph0);
    else        mbar_wait(sb32 + OFF_MBAR + 8, ph1);
    TCG_FENCE_AFTER();
    readout(l, rt0 + NT - 1);
    __syncthreads();
    if (wid == 4) TCG_DEALLOC(tmem, 256);

#else  // ---------------- plain sm_103 fallback (never selected) ----------
    for (int rt = rt0; rt < rt0 + NT; rt++) {
        for (int idx = tid; idx < 128 * 128; idx += 256) {
            int r = idx >> 7, c = idx & 127;
            int gr = rt * 128 + r;
            if (gr >= Ee) continue;
            int cn = col0 + c;
            float acc = bias[cn];
            for (int k = 0; k < 128; k++) {
                float av = __half2float(*(const __half*)((const char*)g_t16 +
                               swz_off(gr >> 7, gr & 127, k)));
                float bv = __half2float(*(const __half*)((const char*)g_w2t16 +
                               swz_off(cn >> 7, cn & 127, k)));
                acc += av * bv;
            }
            g_ewh[(size_t)gr * D2 + cn] = __float2half(acc);
        }
    }
#endif
}

// ---------------- zero helpers --------------------------------------------
__global__ void k_zero_cnt() {
    int idx = blockIdx.x * blockDim.x + threadIdx.x;
    if (idx < Nn) g_cnt[idx] = 0.f;
}
__global__ void k_zero_s2s() {
    int idx = blockIdx.x * blockDim.x + threadIdx.x;
    if (idx < Bb * 2 * DIM) g_qstar[idx] = 0.f;
    if (idx < Bb * DIM) { g_hl[idx] = 0.f; g_cl[idx] = 0.f; }
}

// ---------------- in-degree counts -----------------------------------------
__global__ void k_count(const int* __restrict__ ei) {
    int e = blockIdx.x * blockDim.x + threadIdx.x;
    if (e < Ee) atomicAdd(&g_cnt[ei[Ee + e]], 1.f);
}

// ---------------- per-edge matmul + scatter-add (fp16 ew, warp per edge) ---
__global__ void k_msg(const int* __restrict__ ei) {
    int eg = threadIdx.x >> 5;      // 8 edges per block, warp per edge
    int j = threadIdx.x & 31;       // column-pair index
    int e = blockIdx.x * 8 + eg;
    __shared__ float xs[8][64];
    if (e >= Ee) return;
    int src = ei[e];
    int dst = ei[Ee + e];
    xs[eg][j] = g_out[src * DIM + j];
    xs[eg][j + 32] = g_out[src * DIM + j + 32];
    __syncwarp();
    const __half2* ew = (const __half2*)(g_ewh + (size_t)e * D2) + j;
    float acc0 = 0.f, acc1 = 0.f;
#pragma unroll 16
    for (int i = 0; i < 64; i++) {
        float2 w = __half22float2(ew[i * 32]);
        float xv = xs[eg][i];
        acc0 += xv * w.x;
        acc1 += xv * w.y;
    }
    atomicAdd(&g_agg[dst * DIM + 2 * j], acc0);
    atomicAdd(&g_agg[dst * DIM + 2 * j + 1], acc1);
}

// ---------------- fused node update: conv + GRU gates + GRU + agg-zero -----
__global__ void __launch_bounds__(192)
k_node_update(const float* __restrict__ cr, const float* __restrict__ cb,
              const float* __restrict__ wi, const float* __restrict__ wh,
              const float* __restrict__ bi, const float* __restrict__ bh) {
    int t = threadIdx.x;            // 192 threads
    int n0 = blockIdx.x * 16;
    __shared__ float os[16][DIM], hs[16][DIM], ms[16][DIM];
    __shared__ float gis[16][G3], ghs[16][G3];

    for (int idx = t; idx < 16 * DIM; idx += 192) {
        int r = idx >> 6, d = idx & 63;
        int n = n0 + r;
        float ov = 0.f, hv = 0.f;
        if (n < Nn) { ov = g_out[n * DIM + d]; hv = g_h[n * DIM + d]; }
        os[r][d] = ov;
        hs[r][d] = hv;
    }
    __syncthreads();

    {
        int d = t & 63, p = t >> 6;
        float bd = cb[d];
        for (int r = p; r < 16; r += 3) {
            int n = n0 + r;
            float acc = 0.f;
#pragma unroll 8
            for (int i = 0; i < 64; i++) acc += os[r][i] * cr[i * DIM + d];
            float mval = 0.f;
            if (n < Nn) {
                float c = fmaxf(g_cnt[n], 1.f);
                mval = fmaxf(g_agg[n * DIM + d] / c + acc + bd, 0.f);
                g_agg[n * DIM + d] = 0.f;   // ready for next msg step
            }
            ms[r][d] = mval;
        }
    }
    __syncthreads();

    {
        int g = t;
        float ai[16], ah[16];
#pragma unroll
        for (int r = 0; r < 16; r++) { ai[r] = 0.f; ah[r] = 0.f; }
        for (int i = 0; i < 64; i++) {
            float wiv = wi[i * G3 + g], whv = wh[i * G3 + g];
#pragma unroll
            for (int r = 0; r < 16; r++) {
                ai[r] += ms[r][i] * wiv;
                ah[r] += hs[r][i] * whv;
            }
        }
        float biv = bi[g], bhv = bh[g];
#pragma unroll
        for (int r = 0; r < 16; r++) {
            gis[r][g] = ai[r] + biv;
            ghs[r][g] = ah[r] + bhv;
        }
    }
    __syncthreads();

    {
        int d = t & 63, p = t >> 6;
        for (int r = p; r < 16; r += 3) {
            int n = n0 + r;
            if (n >= Nn) continue;
            float rg = sigm(gis[r][d] + ghs[r][d]);
            float z = sigm(gis[r][64 + d] + ghs[r][64 + d]);
            float nn = tanhf(gis[r][128 + d] + rg * ghs[r][128 + d]);
            float h = hs[r][d];
            float hn = (1.f - z) * nn + z * h;
            g_h[n * DIM + d] = hn;
            g_out[n * DIM + d] = hn;
        }
    }
}

// ---------------- per-graph node ranges (batch is sorted) ------------------
__global__ void k_ranges(const int* __restrict__ batch) {
    int n = blockIdx.x * blockDim.x + threadIdx.x;
    if (n >= Nn) return;
    int bn = batch[n];
    int bp = (n == 0) ? -1 : batch[n - 1];
    for (int b = bp + 1; b <= bn; b++) g_gs[b] = n;
    if (n == Nn - 1)
        for (int b = bn + 1; b <= Bb; b++) g_gs[b] = Nn;
}

// ---------------- Set2Set LSTM cell ----------------------------------------
__global__ void k_lstm(const float* __restrict__ wi, const float* __restrict__ wh,
                       const float* __restrict__ bi, const float* __restrict__ bh) {
    int b = blockIdx.x;
    int g = threadIdx.x;            // 256 threads
    __shared__ float qs[128], hls[64], gate[256];
    if (g < 128) qs[g] = g_qstar[b * 128 + g];
    if (g < 64) hls[g] = g_hl[b * 64 + g];
    __syncthreads();
    float acc = bi[g] + bh[g];
    for (int i = 0; i < 128; i++) acc += qs[i] * wi[i * 256 + g];
    for (int i = 0; i < 64; i++) acc += hls[i] * wh[i * 256 + g];
    gate[g] = acc;
    __syncthreads();
    if (g < 64) {
        float iv = sigm(gate[g]);
        float fv = sigm(gate[64 + g]);
        float gv = tanhf(gate[128 + g]);
        float ov = sigm(gate[192 + g]);
        float c = fv * g_cl[b * 64 + g] + iv * gv;
        g_cl[b * 64 + g] = c;
        g_hl[b * 64 + g] = ov * tanhf(c);
    }
}

// ---------------- Set2Set attention + readout ------------------------------
__global__ void k_attend() {
    int b = blockIdx.x;
    int t = threadIdx.x;            // 256 threads
    __shared__ float q[64];
    __shared__ float red[256];
    __shared__ float rs[4][64];
    if (t < 64) q[t] = g_hl[b * 64 + t];
    int s = g_gs[b], epos = g_gs[b + 1];
    __syncthreads();

    float lmax = -INFINITY;
    for (int n = s + t; n < epos; n += 256) {
        const float* orow = g_out + (size_t)n * 64;
        float acc = 0.f;
#pragma unroll
        for (int d = 0; d < 64; d++) acc += orow[d] * q[d];
        g_escr[n] = acc;
        lmax = fmaxf(lmax, acc);
    }
    red[t] = lmax;
    __syncthreads();
    for (int st = 128; st > 0; st >>= 1) {
        if (t < st) red[t] = fmaxf(red[t], red[t + st]);
        __syncthreads();
    }
    float emax = red[0];
    __syncthreads();

    float lsum = 0.f;
    for (int n = s + t; n < epos; n += 256) {
        float a = expf(g_escr[n] - emax);
        g_escr[n] = a;
        lsum += a;
    }
    red[t] = lsum;
    __syncthreads();
    for (int st = 128; st > 0; st >>= 1) {
        if (t < st) red[t] += red[t + st];
        __syncthreads();
    }
    float inv = 1.f / fmaxf(red[0], 1e-16f);
    __syncthreads();

    int d = t & 63, slot = t >> 6;
    float acc = 0.f;
    for (int n = s + slot; n < epos; n += 4) acc += g_escr[n] * g_out[(size_t)n * 64 + d];
    rs[slot][d] = acc;
    __syncthreads();
    if (t < 64) {
        float r = (rs[0][t] + rs[1][t] + rs[2][t] + rs[3][t]) * inv;
        g_qstar[b * 128 + t] = q[t];
        g_qstar[b * 128 + 64 + t] = r;
    }
}

// ---------------- output head ----------------------------------------------
__global__ void k_head(const float* __restrict__ w1, const float* __restrict__ b1,
                       const float* __restrict__ w2, const float* __restrict__ b2,
                       float* __restrict__ out) {
    int b = blockIdx.x;
    int d = threadIdx.x;            // 64 threads
    __shared__ float qs[128];
    __shared__ float red[64];
    qs[d] = g_qstar[b * 128 + d];
    qs[64 + d] = g_qstar[b * 128 + 64 + d];
    __syncthreads();
    float acc = b1[d];
    for (int i = 0; i < 128; i++) acc += qs[i] * w1[i * 64 + d];
    float h1 = fmaxf(acc, 0.f);
    red[d] = h1 * w2[d];
    __syncthreads();
    for (int st = 32; st > 0; st >>= 1) {
        if (d < st) red[d] += red[d + st];
        __syncthreads();
    }
    if (d == 0) out[b] = red[0] + b2[0];
}

// ---------------- launch ----------------------------------------------------
extern "C" void kernel_launch(void* const* d_in, const int* in_sizes, int n_in,
                              void* d_out, int out_size) {
    const float* x        = (const float*)d_in[0];
    const float* ea       = (const float*)d_in[1];
    const int*   ei       = (const int*)d_in[2];
    const int*   batch    = (const int*)d_in[3];
    const float* lin0_w   = (const float*)d_in[4];
    const float* lin0_b   = (const float*)d_in[5];
    const float* mlp_w1   = (const float*)d_in[6];
    const float* mlp_b1   = (const float*)d_in[7];
    const float* mlp_w2   = (const float*)d_in[8];
    const float* mlp_b2   = (const float*)d_in[9];
    const float* conv_root= (const float*)d_in[10];
    const float* conv_bias= (const float*)d_in[11];
    const float* gru_wi   = (const float*)d_in[12];
    const float* gru_wh   = (const float*)d_in[13];
    const float* gru_bi   = (const float*)d_in[14];
    const float* gru_bh   = (const float*)d_in[15];
    const float* lstm_wi  = (const float*)d_in[16];
    const float* lstm_wh  = (const float*)d_in[17];
    const float* lstm_bi  = (const float*)d_in[18];
    const float* lstm_bh  = (const float*)d_in[19];
    const float* lin1_w   = (const float*)d_in[20];
    const float* lin1_b   = (const float*)d_in[21];
    const float* lin2_w   = (const float*)d_in[22];
    const float* lin2_b   = (const float*)d_in[23];
    float* out = (float*)d_out;

    cudaFuncSetAttribute(k_ew_mma, cudaFuncAttributeMaxDynamicSharedMemorySize, SMEM_EW);

    // k_ew_mma at launch idx 3: that's the slot ncu -s/-c captures
    k_lin0<<<(Nn * DIM + 255) / 256, 256>>>(x, lin0_w, lin0_b);
    k_edge_hidden<<<(Epad * MLPH + 255) / 256, 256>>>(ea, mlp_w1, mlp_b1);
    {
        dim3 tg(D2 / 32, MLPH / 32);
        k_prep_w2t<<<tg, 256>>>(mlp_w2);
    }
    {
        dim3 grid(D2 / TN, (RTILES + TPB - 1) / TPB);
        k_ew_mma<<<grid, 256, SMEM_EW>>>(mlp_b2);
    }
    k_zero_cnt<<<(Nn + 255) / 256, 256>>>();
    k_count<<<(Ee + 255) / 256, 256>>>(ei);

    for (int s = 0; s < 3; s++) {
        k_msg<<<(Ee + 7) / 8, 256>>>(ei);
        k_node_update<<<(Nn + 15) / 16, 192>>>(conv_root, conv_bias, gru_wi, gru_wh,
                                               gru_bi, gru_bh);
    }

    k_ranges<<<(Nn + 255) / 256, 256>>>(batch);
    k_zero_s2s<<<(Bb * 2 * DIM + 255) / 256, 256>>>();
    for (int it = 0; it < 3; it++) {
        k_lstm<<<Bb, 256>>>(lstm_wi, lstm_wh, lstm_bi, lstm_bh);
        k_attend<<<Bb, 256>>>();
    }
    k_head<<<Bb, 64>>>(lin1_w, lin1_b, lin2_w, lin2_b, out);
}